// round 1
// baseline (speedup 1.0000x reference)
#include <cuda_runtime.h>
#include <cuda_bf16.h>

// VectorQuantizer (per-dimension scalar codebooks)
//   z:         [B, D]  float32   (B=2048, D=128)
//   codebooks: [D, K]  float32   (K=512)
// outputs: loss (scalar mean((q-z)^2)) and quantized_st (== quantized numerically)

#define VQ_D 128
#define VQ_K 512
#define VQ_THREADS 256
#define VQ_BPT 4   // batch elements per thread

// partial sums: grid is (D, CHUNKS); CHUNKS = B/(THREADS*BPT) = 2 for B=2048.
// Max partials we ever need: D * 8 chunks headroom.
__device__ float g_partials[1024];

__global__ void __launch_bounds__(VQ_THREADS)
vq_main_kernel(const float* __restrict__ z,
               const float* __restrict__ cb,
               float* __restrict__ qout,   // may be null
               int nb)                     // batch size
{
    __shared__ float4 scb[VQ_K / 4];
    __shared__ float sred[VQ_THREADS];

    const int d   = blockIdx.x;
    const int tid = threadIdx.x;

    // stage codebook row d (512 floats) into smem
    const float4* row4 = reinterpret_cast<const float4*>(cb + d * VQ_K);
    for (int i = tid; i < VQ_K / 4; i += VQ_THREADS)
        scb[i] = row4[i];
    __syncthreads();

    const int bbase = blockIdx.y * (VQ_THREADS * VQ_BPT);

    float zv[VQ_BPT];
    float bd[VQ_BPT];   // best |z - c|
    float bc[VQ_BPT];   // best code value
    bool  valid[VQ_BPT];

#pragma unroll
    for (int j = 0; j < VQ_BPT; j++) {
        int b = bbase + j * VQ_THREADS + tid;
        valid[j] = (b < nb);
        zv[j] = valid[j] ? z[b * VQ_D + d] : 0.0f;
        bd[j] = 3.4e38f;
        bc[j] = 0.0f;
    }

    // scan all K codes, ascending k => strict '<' keeps first argmin (tie semantics)
#pragma unroll 4
    for (int k4 = 0; k4 < VQ_K / 4; k4++) {
        float4 c = scb[k4];
#pragma unroll
        for (int j = 0; j < VQ_BPT; j++) {
            float a;
            a = fabsf(zv[j] - c.x); if (a < bd[j]) { bd[j] = a; bc[j] = c.x; }
            a = fabsf(zv[j] - c.y); if (a < bd[j]) { bd[j] = a; bc[j] = c.y; }
            a = fabsf(zv[j] - c.z); if (a < bd[j]) { bd[j] = a; bc[j] = c.z; }
            a = fabsf(zv[j] - c.w); if (a < bd[j]) { bd[j] = a; bc[j] = c.w; }
        }
    }

    // write quantized + accumulate local squared error
    float acc = 0.0f;
#pragma unroll
    for (int j = 0; j < VQ_BPT; j++) {
        if (valid[j]) {
            int b = bbase + j * VQ_THREADS + tid;
            if (qout) qout[b * VQ_D + d] = bc[j];
            float e = bc[j] - zv[j];
            acc += e * e;
        }
    }

    // deterministic block tree reduction
    sred[tid] = acc;
    __syncthreads();
    for (int s = VQ_THREADS / 2; s > 0; s >>= 1) {
        if (tid < s) sred[tid] += sred[tid + s];
        __syncthreads();
    }
    if (tid == 0)
        g_partials[blockIdx.y * gridDim.x + blockIdx.x] = sred[0];
}

__global__ void vq_loss_kernel(float* __restrict__ loss_out, int n_partials, float inv_n)
{
    __shared__ float sred[VQ_THREADS];
    int tid = threadIdx.x;
    float acc = 0.0f;
    for (int i = tid; i < n_partials; i += VQ_THREADS)
        acc += g_partials[i];
    sred[tid] = acc;
    __syncthreads();
    for (int s = VQ_THREADS / 2; s > 0; s >>= 1) {
        if (tid < s) sred[tid] += sred[tid + s];
        __syncthreads();
    }
    if (tid == 0)
        *loss_out = sred[0] * inv_n;
}

extern "C" void kernel_launch(void* const* d_in, const int* in_sizes, int n_in,
                              void* d_out, int out_size)
{
    const float* z  = (const float*)d_in[0];   // [B, D]
    const float* cb = (const float*)d_in[1];   // [D, K]
    float* out = (float*)d_out;

    const int nb = in_sizes[0] / VQ_D;         // B
    const int bd_total = nb * VQ_D;

    // Output layout dispatch: reference returns (loss, quantized_st)
    float* loss_ptr = nullptr;
    float* q_ptr    = nullptr;
    if (out_size == bd_total + 1) { loss_ptr = out; q_ptr = out + 1; }
    else if (out_size == bd_total) { q_ptr = out; }
    else if (out_size == 1)        { loss_ptr = out; }
    else                           { q_ptr = out; }   // fallback: quantized-first

    int chunks = (nb + VQ_THREADS * VQ_BPT - 1) / (VQ_THREADS * VQ_BPT);
    if (chunks > 8) chunks = 8; // guard g_partials bound (won't trigger for B=2048)

    dim3 grid(VQ_D, chunks);
    vq_main_kernel<<<grid, VQ_THREADS>>>(z, cb, q_ptr, nb);

    if (loss_ptr) {
        float inv_n = 1.0f / (float)bd_total;
        vq_loss_kernel<<<1, VQ_THREADS>>>(loss_ptr, VQ_D * chunks, inv_n);
    }
}

// round 2
// speedup vs baseline: 1.8906x; 1.8906x over previous
#include <cuda_runtime.h>
#include <cuda_bf16.h>

// VectorQuantizer (per-dimension scalar codebooks), single fused kernel.
//   z:         [B, D]  float32   (B=2048, D=128)
//   codebooks: [D, K]  float32   (K=512)
// For each (b,d): nearest scalar code via sorted-codebook binary search.
// Loss = mean((q - z)^2) finalized by the last block (deterministic order).

#define VQ_D 128
#define VQ_K 512
#define VQ_THREADS 256
#define VQ_BPT 8          // 256*8 = 2048 batch elements per block

__device__ float        g_partials[VQ_D];
__device__ unsigned int g_count = 0;

__global__ void __launch_bounds__(VQ_THREADS)
vq_fused_kernel(const float* __restrict__ z,
                const float* __restrict__ cb,
                float* __restrict__ qout,      // may be null
                float* __restrict__ loss_out,  // may be null
                int nb, float inv_n)
{
    __shared__ float s[VQ_K];
    __shared__ float swred[VQ_THREADS / 32];
    __shared__ float sblock;
    __shared__ int   s_is_last;

    const int d    = blockIdx.x;
    const int tid  = threadIdx.x;
    const int lane = tid & 31;
    const int wid  = tid >> 5;

    // ---- stage codebook row d (512 floats) ----
    if (tid < VQ_K / 4) {
        reinterpret_cast<float4*>(s)[tid] =
            reinterpret_cast<const float4*>(cb + d * VQ_K)[tid];
    }

    // ---- bitonic sort (ascending) of s[0..511] ----
    for (int k = 2; k <= VQ_K; k <<= 1) {
        for (int j = k >> 1; j > 0; j >>= 1) {
            __syncthreads();
#pragma unroll
            for (int t = 0; t < VQ_K / VQ_THREADS; t++) {
                int i   = tid + t * VQ_THREADS;
                int ixj = i ^ j;
                if (ixj > i) {
                    float a = s[i], b = s[ixj];
                    bool up = ((i & k) == 0);
                    if ((a > b) == up) { s[i] = b; s[ixj] = a; }
                }
            }
        }
    }
    __syncthreads();

    // ---- binary search for each batch element ----
    float acc = 0.0f;
#pragma unroll
    for (int jj = 0; jj < VQ_BPT; jj++) {
        int b = jj * VQ_THREADS + tid;
        if (b < nb) {
            float zv = z[b * VQ_D + d];

            // branchless lower_bound: pos = #elements < zv
            int pos = 0;
#pragma unroll
            for (int step = VQ_K / 2; step >= 1; step >>= 1)
                if (s[pos + step - 1] < zv) pos += step;

            int li = pos > 0 ? pos - 1 : 0;
            int ri = pos < VQ_K ? pos : VQ_K - 1;
            float lv = s[li];
            float rv = s[ri];
            float dl = (pos > 0)     ? (zv - lv) : 3.4e38f;  // left <  zv
            float dr = (pos < VQ_K)  ? (rv - zv) : 3.4e38f;  // right >= zv
            float q  = (dl <= dr) ? lv : rv;

            if (qout) qout[b * VQ_D + d] = zv + (q - zv);  // match ST rounding
            float e = q - zv;
            acc += e * e;
        }
    }

    // ---- block loss reduction (deterministic tree) ----
#pragma unroll
    for (int o = 16; o > 0; o >>= 1)
        acc += __shfl_down_sync(0xffffffffu, acc, o);
    if (lane == 0) swred[wid] = acc;
    __syncthreads();
    if (tid == 0) {
        float t = 0.0f;
#pragma unroll
        for (int w = 0; w < VQ_THREADS / 32; w++) t += swred[w];
        sblock = t;
    }
    __syncthreads();

    // ---- cross-block finalize: last block sums all partials ----
    if (tid == 0) {
        g_partials[d] = sblock;
        __threadfence();
        unsigned int c = atomicAdd(&g_count, 1u);
        s_is_last = (c == (unsigned int)(gridDim.x - 1));
    }
    __syncthreads();

    if (s_is_last) {
        if (tid < 32) {
            __threadfence();
            float t = 0.0f;
#pragma unroll
            for (int i = 0; i < VQ_D / 32; i++)
                t += g_partials[lane + i * 32];
#pragma unroll
            for (int o = 16; o > 0; o >>= 1)
                t += __shfl_down_sync(0xffffffffu, t, o);
            if (lane == 0) {
                if (loss_out) *loss_out = t * inv_n;
                g_count = 0;  // reset for next graph replay
            }
        }
    }
}

extern "C" void kernel_launch(void* const* d_in, const int* in_sizes, int n_in,
                              void* d_out, int out_size)
{
    const float* z  = (const float*)d_in[0];   // [B, D]
    const float* cb = (const float*)d_in[1];   // [D, K]
    float* out = (float*)d_out;

    const int nb       = in_sizes[0] / VQ_D;   // B
    const int bd_total = nb * VQ_D;

    float* loss_ptr = nullptr;
    float* q_ptr    = nullptr;
    if (out_size == bd_total + 1)      { loss_ptr = out; q_ptr = out + 1; }
    else if (out_size == bd_total)     { q_ptr = out; }
    else if (out_size == 1)            { loss_ptr = out; }
    else                               { q_ptr = out; }

    float inv_n = 1.0f / (float)bd_total;
    vq_fused_kernel<<<VQ_D, VQ_THREADS>>>(z, cb, q_ptr, loss_ptr, nb, inv_n);
}